// round 4
// baseline (speedup 1.0000x reference)
#include <cuda_runtime.h>
#include <math.h>

#define BB 256
#define NN 1000
#define DD 256
#define HH 8
#define DHH 32
#define NEG (-1000000000.0f)

// Intermediates (device globals: no allocation allowed)
__device__ float g_q1[BB * DD];      // glimpse_q
__device__ float g_q2[BB * DD];      // head_in
__device__ float g_att1[BB * DD];    // mha(glimpse_q)
__device__ float g_att2[BB * DD];    // mha(head_in)
__device__ float g_glimpse[BB * DD]; // att1 @ W_out

// ---------------------------------------------------------------------------
// Phase 1: step_context = concat(cur, graph_ctx, dyn) @ W_ctx  (per-batch matvec)
// grid = B, block = 256.  Thread t computes output cols t and t+256.
// ---------------------------------------------------------------------------
__global__ void ctx_kernel(const float* __restrict__ node_emb,
                           const float* __restrict__ graph_ctx,
                           const float* __restrict__ cap,
                           const float* __restrict__ rd,
                           const float* __restrict__ rn,
                           const float* __restrict__ Wc,
                           const int* __restrict__ head) {
    int b = blockIdx.x, t = threadIdx.x;
    __shared__ float x[515];
    int hd = head[b];
    x[t]       = node_emb[((size_t)b * NN + hd) * DD + t];
    x[256 + t] = graph_ctx[b * DD + t];
    if (t == 0) { x[512] = cap[b]; x[513] = rd[b]; x[514] = rn[b]; }
    __syncthreads();

    float a0 = 0.f, a1 = 0.f;
#pragma unroll 5
    for (int i = 0; i < 515; i++) {
        float xv = x[i];
        const float* wr = Wc + (size_t)i * 512;
        a0 = fmaf(xv, wr[t], a0);
        a1 = fmaf(xv, wr[t + 256], a1);
    }
    g_q1[b * DD + t] = a0;
    g_q2[b * DD + t] = a1;
}

// ---------------------------------------------------------------------------
// Phase 2: dual-query MHA per (b, h).  grid = (H, B), block = 256.
// One pass over K computes both queries' scores; one pass over V accumulates
// both outputs (V read once).
// ---------------------------------------------------------------------------
__global__ void attn_kernel(const float* __restrict__ K,
                            const float* __restrict__ V,
                            const int* __restrict__ feasible) {
    int h = blockIdx.x, b = blockIdx.y;
    int tid = threadIdx.x;

    __shared__ float s1[NN];
    __shared__ float s2[NN];
    __shared__ unsigned char feas[NN];
    __shared__ float q1[DHH], q2[DHH];
    __shared__ float red[256];
    __shared__ int ired[256];

    if (tid < DHH) {
        q1[tid] = g_q1[b * DD + h * DHH + tid];
        q2[tid] = g_q2[b * DD + h * DHH + tid];
    }

    // feasibility + no_feasible fix
    int anyf = 0;
    for (int n = tid; n < NN; n += 256) {
        int f = feasible[b * NN + n];
        feas[n] = (unsigned char)(f != 0);
        anyf |= f;
    }
    ired[tid] = anyf;
    __syncthreads();
    for (int s = 128; s > 0; s >>= 1) {
        if (tid < s) ired[tid] |= ired[tid + s];
        __syncthreads();
    }
    if (tid == 0 && ired[0] == 0) feas[0] = 1;
    __syncthreads();

    const float scale = 0.17677669529663687f; // 1/sqrt(32)
    float m1l = NEG, m2l = NEG;
    const float4* Kb = (const float4*)(K + (size_t)(b * HH + h) * NN * DHH);
    for (int n = tid; n < NN; n += 256) {
        const float4* kr = Kb + n * 8;
        float d1 = 0.f, d2 = 0.f;
#pragma unroll
        for (int i = 0; i < 8; i++) {
            float4 kv = kr[i];
            d1 = fmaf(kv.x, q1[4 * i + 0], d1);
            d1 = fmaf(kv.y, q1[4 * i + 1], d1);
            d1 = fmaf(kv.z, q1[4 * i + 2], d1);
            d1 = fmaf(kv.w, q1[4 * i + 3], d1);
            d2 = fmaf(kv.x, q2[4 * i + 0], d2);
            d2 = fmaf(kv.y, q2[4 * i + 1], d2);
            d2 = fmaf(kv.z, q2[4 * i + 2], d2);
            d2 = fmaf(kv.w, q2[4 * i + 3], d2);
        }
        float v1 = feas[n] ? d1 * scale : NEG;
        float v2 = feas[n] ? d2 * scale : NEG;
        s1[n] = v1; s2[n] = v2;
        m1l = fmaxf(m1l, v1);
        m2l = fmaxf(m2l, v2);
    }

    // reduce maxes
    red[tid] = m1l; __syncthreads();
    for (int s = 128; s > 0; s >>= 1) { if (tid < s) red[tid] = fmaxf(red[tid], red[tid + s]); __syncthreads(); }
    float m1 = red[0]; __syncthreads();
    red[tid] = m2l; __syncthreads();
    for (int s = 128; s > 0; s >>= 1) { if (tid < s) red[tid] = fmaxf(red[tid], red[tid + s]); __syncthreads(); }
    float m2 = red[0]; __syncthreads();

    // exponentiate, reduce sums
    float z1l = 0.f, z2l = 0.f;
    for (int n = tid; n < NN; n += 256) {
        float p1 = expf(s1[n] - m1);
        float p2 = expf(s2[n] - m2);
        s1[n] = p1; s2[n] = p2;
        z1l += p1; z2l += p2;
    }
    red[tid] = z1l; __syncthreads();
    for (int s = 128; s > 0; s >>= 1) { if (tid < s) red[tid] += red[tid + s]; __syncthreads(); }
    float Z1 = red[0]; __syncthreads();
    red[tid] = z2l; __syncthreads();
    for (int s = 128; s > 0; s >>= 1) { if (tid < s) red[tid] += red[tid + s]; __syncthreads(); }
    float Z2 = red[0]; __syncthreads();

    // V accumulation: warp w handles n = w, w+8, ... (125 iters); lane = d.
    int w = tid >> 5, lane = tid & 31;
    const float* Vb = V + (size_t)(b * HH + h) * NN * DHH;
    float a1 = 0.f, a2 = 0.f;
#pragma unroll 5
    for (int n = w; n < NN; n += 8) {
        float v = Vb[n * DHH + lane];
        a1 = fmaf(s1[n], v, a1);
        a2 = fmaf(s2[n], v, a2);
    }
    __syncthreads();              // everyone done reading p from s1/s2
    s1[tid] = a1;                 // reuse shared for cross-warp reduce
    s2[tid] = a2;
    __syncthreads();
    if (tid < 64) {
        int qi = tid >> 5, l = tid & 31;
        const float* sr = qi ? s2 : s1;
        float sum = 0.f;
#pragma unroll
        for (int ww = 0; ww < 8; ww++) sum += sr[ww * 32 + l];
        if (qi == 0) g_att1[b * DD + h * DHH + l] = sum / Z1;
        else         g_att2[b * DD + h * DHH + l] = sum / Z2;
    }
}

// ---------------------------------------------------------------------------
// Phase 2.5: glimpse = att1 @ W_out ; head_encoding = att2 @ W_sa
// grid = B, block = 256 (thread t = output col t)
// ---------------------------------------------------------------------------
__global__ void proj_kernel(const float* __restrict__ Wout,
                            const float* __restrict__ Wsa,
                            float* __restrict__ out_head) {
    int b = blockIdx.x, t = threadIdx.x;
    __shared__ float a1[DD], a2[DD];
    a1[t] = g_att1[b * DD + t];
    a2[t] = g_att2[b * DD + t];
    __syncthreads();
    float g = 0.f, he = 0.f;
#pragma unroll 8
    for (int i = 0; i < DD; i++) {
        g  = fmaf(a1[i], Wout[i * DD + t], g);
        he = fmaf(a2[i], Wsa[i * DD + t], he);
    }
    g_glimpse[b * DD + t] = g;
    out_head[b * DD + t] = he;
}

// ---------------------------------------------------------------------------
// Phase 3: logits + tanh clip + mask + log_softmax.  grid = B, block = 256.
// ---------------------------------------------------------------------------
__global__ void logits_kernel(const float* __restrict__ LK,
                              const int* __restrict__ feasible,
                              float* __restrict__ out_logp) {
    int b = blockIdx.x, tid = threadIdx.x;
    __shared__ float gl[DD];
    __shared__ float lg[NN];
    __shared__ unsigned char feas[NN];
    __shared__ float red[256];
    __shared__ int ired[256];

    gl[tid] = g_glimpse[b * DD + tid];

    int anyf = 0;
    for (int n = tid; n < NN; n += 256) {
        int f = feasible[b * NN + n];
        feas[n] = (unsigned char)(f != 0);
        anyf |= f;
    }
    ired[tid] = anyf;
    __syncthreads();
    for (int s = 128; s > 0; s >>= 1) {
        if (tid < s) ired[tid] |= ired[tid + s];
        __syncthreads();
    }
    if (tid == 0 && ired[0] == 0) feas[0] = 1;
    __syncthreads();

    const float inv = 0.0625f; // 1/sqrt(256)
    float ml = NEG;
    const float4* LKb = (const float4*)(LK + (size_t)b * NN * DD);
    const float4* glv = (const float4*)gl;
    for (int n = tid; n < NN; n += 256) {
        const float4* r = LKb + n * 64;
        float dsum = 0.f;
#pragma unroll 16
        for (int i = 0; i < 64; i++) {
            float4 kv = r[i];
            float4 gv = glv[i];
            dsum = fmaf(kv.x, gv.x, dsum);
            dsum = fmaf(kv.y, gv.y, dsum);
            dsum = fmaf(kv.z, gv.z, dsum);
            dsum = fmaf(kv.w, gv.w, dsum);
        }
        float l = 10.0f * tanhf(dsum * inv);
        l = feas[n] ? l : NEG;
        lg[n] = l;
        ml = fmaxf(ml, l);
    }

    red[tid] = ml; __syncthreads();
    for (int s = 128; s > 0; s >>= 1) { if (tid < s) red[tid] = fmaxf(red[tid], red[tid + s]); __syncthreads(); }
    float m = red[0]; __syncthreads();

    float zl = 0.f;
    for (int n = tid; n < NN; n += 256) zl += expf(lg[n] - m);
    red[tid] = zl; __syncthreads();
    for (int s = 128; s > 0; s >>= 1) { if (tid < s) red[tid] += red[tid + s]; __syncthreads(); }
    float lse = m + logf(red[0]);
    __syncthreads();

    for (int n = tid; n < NN; n += 256)
        out_logp[b * NN + n] = lg[n] - lse;
}

// ---------------------------------------------------------------------------
extern "C" void kernel_launch(void* const* d_in, const int* in_sizes, int n_in,
                              void* d_out, int out_size) {
    const float* node_emb  = (const float*)d_in[0];
    const float* graph_ctx = (const float*)d_in[1];
    const float* K         = (const float*)d_in[2];
    const float* V         = (const float*)d_in[3];
    const float* LK        = (const float*)d_in[4];
    const float* cap       = (const float*)d_in[5];
    const float* rd        = (const float*)d_in[6];
    const float* rn        = (const float*)d_in[7];
    const float* Wc        = (const float*)d_in[8];
    const float* Wout      = (const float*)d_in[9];
    const float* Wsa       = (const float*)d_in[10];
    const int*   head      = (const int*)d_in[11];
    const int*   feasible  = (const int*)d_in[12];
    float* out = (float*)d_out;

    ctx_kernel<<<BB, 256>>>(node_emb, graph_ctx, cap, rd, rn, Wc, head);
    attn_kernel<<<dim3(HH, BB), 256>>>(K, V, feasible);
    proj_kernel<<<BB, 256>>>(Wout, Wsa, out + BB * NN);
    logits_kernel<<<BB, 256>>>(LK, feasible, out);
}

// round 5
// speedup vs baseline: 1.2184x; 1.2184x over previous
#include <cuda_runtime.h>
#include <math.h>

#define BB 256
#define NN 1000
#define DD 256
#define HH 8
#define DHH 32
#define NEG (-1000000000.0f)

// Intermediates (device globals: no allocation allowed)
__device__ float g_q1[BB * DD];       // glimpse_q
__device__ float g_q2[BB * DD];       // head_in
__device__ float g_att1[BB * DD];     // mha(glimpse_q)
__device__ float g_att2[BB * DD];     // mha(head_in)
__device__ float g_glimpse[BB * DD];  // att1 @ W_out
__device__ unsigned char g_feas[BB * NN];

// ---------------------------------------------------------------------------
// Phase 0: feasibility mask + no-feasible fix, computed ONCE.
// grid = B, block = 256.
// ---------------------------------------------------------------------------
__global__ void feas_kernel(const int* __restrict__ feasible) {
    int b = blockIdx.x, t = threadIdx.x;
    __shared__ int w8[8];
    int any = 0;
    for (int n = t; n < NN; n += 256) {
        int f = feasible[b * NN + n];
        g_feas[b * NN + n] = (unsigned char)(f != 0);
        any |= f;
    }
#pragma unroll
    for (int o = 16; o; o >>= 1) any |= __shfl_xor_sync(0xffffffffu, any, o);
    if ((t & 31) == 0) w8[t >> 5] = any;
    __syncthreads();
    if (t == 0) {
        int a = 0;
#pragma unroll
        for (int i = 0; i < 8; i++) a |= w8[i];
        if (!a) g_feas[b * NN] = 1;
    }
}

// ---------------------------------------------------------------------------
// Phase 1 (tiled): step_context = concat(cur, graph_ctx, dyn) @ W_ctx
// grid = (16 batch-groups, 16 col-chunks), block = 256, dynamic smem ~99KB.
// Each block: 16 batches x 32 output cols; W chunk loaded once into smem.
// ---------------------------------------------------------------------------
__global__ void ctx2_kernel(const float* __restrict__ node_emb,
                            const float* __restrict__ graph_ctx,
                            const float* __restrict__ cap,
                            const float* __restrict__ rd,
                            const float* __restrict__ rn,
                            const float* __restrict__ Wc,
                            const int* __restrict__ head) {
    extern __shared__ float sm[];
    float* Ws = sm;              // 515*32
    float* xs = sm + 515 * 32;   // 16*515
    int bg = blockIdx.x, cc = blockIdx.y;
    int t = threadIdx.x;
    int j0 = cc * 32, b0 = bg * 16;

    for (int idx = t; idx < 515 * 32; idx += 256) {
        int r = idx >> 5, c = idx & 31;
        Ws[idx] = Wc[r * 512 + j0 + c];
    }
    for (int b = 0; b < 16; b++) {
        int bA = b0 + b;
        int hd = head[bA];
        const float* emb = node_emb + ((size_t)bA * NN + hd) * DD;
        const float* gc = graph_ctx + bA * DD;
        for (int i = t; i < 515; i += 256) {
            float v;
            if (i < 256) v = emb[i];
            else if (i < 512) v = gc[i - 256];
            else v = (i == 512) ? cap[bA] : (i == 513) ? rd[bA] : rn[bA];
            xs[b * 515 + i] = v;
        }
    }
    __syncthreads();

    int c = t & 31, bp = t >> 5;
    const float* xA = xs + bp * 515;
    const float* xB = xs + (bp + 8) * 515;
    float a0 = 0.f, a1 = 0.f;
#pragma unroll 5
    for (int i = 0; i < 515; i++) {
        float w = Ws[i * 32 + c];
        a0 = fmaf(xA[i], w, a0);
        a1 = fmaf(xB[i], w, a1);
    }
    int j = j0 + c;
    int bA = b0 + bp, bB = bA + 8;
    if (j < 256) {
        g_q1[bA * DD + j] = a0;
        g_q1[bB * DD + j] = a1;
    } else {
        g_q2[bA * DD + j - 256] = a0;
        g_q2[bB * DD + j - 256] = a1;
    }
}

// ---------------------------------------------------------------------------
// Phase 2: dual-query MHA per (b, h).  grid = (H, B), block = 256.
// ---------------------------------------------------------------------------
__device__ __forceinline__ float blk_max(float v, float* red, int tid) {
#pragma unroll
    for (int o = 16; o; o >>= 1) v = fmaxf(v, __shfl_xor_sync(0xffffffffu, v, o));
    if ((tid & 31) == 0) red[tid >> 5] = v;
    __syncthreads();
    float r = red[0];
#pragma unroll
    for (int i = 1; i < 8; i++) r = fmaxf(r, red[i]);
    __syncthreads();
    return r;
}
__device__ __forceinline__ float blk_sum(float v, float* red, int tid) {
#pragma unroll
    for (int o = 16; o; o >>= 1) v += __shfl_xor_sync(0xffffffffu, v, o);
    if ((tid & 31) == 0) red[tid >> 5] = v;
    __syncthreads();
    float r = red[0];
#pragma unroll
    for (int i = 1; i < 8; i++) r += red[i];
    __syncthreads();
    return r;
}

__global__ void attn_kernel(const float* __restrict__ K,
                            const float* __restrict__ V) {
    int h = blockIdx.x, b = blockIdx.y;
    int tid = threadIdx.x;

    __shared__ float s1[NN];
    __shared__ float s2[NN];
    __shared__ float q1[DHH], q2[DHH];
    __shared__ float red[8];

    if (tid < DHH) {
        q1[tid] = g_q1[b * DD + h * DHH + tid];
        q2[tid] = g_q2[b * DD + h * DHH + tid];
    }
    __syncthreads();

    const float scale = 0.17677669529663687f; // 1/sqrt(32)
    float m1l = NEG, m2l = NEG;
    const float4* Kb = (const float4*)(K + (size_t)(b * HH + h) * NN * DHH);
    const unsigned char* fb = g_feas + b * NN;
    for (int n = tid; n < NN; n += 256) {
        const float4* kr = Kb + n * 8;
        float d1 = 0.f, d2 = 0.f;
#pragma unroll
        for (int i = 0; i < 8; i++) {
            float4 kv = kr[i];
            d1 = fmaf(kv.x, q1[4 * i + 0], d1);
            d1 = fmaf(kv.y, q1[4 * i + 1], d1);
            d1 = fmaf(kv.z, q1[4 * i + 2], d1);
            d1 = fmaf(kv.w, q1[4 * i + 3], d1);
            d2 = fmaf(kv.x, q2[4 * i + 0], d2);
            d2 = fmaf(kv.y, q2[4 * i + 1], d2);
            d2 = fmaf(kv.z, q2[4 * i + 2], d2);
            d2 = fmaf(kv.w, q2[4 * i + 3], d2);
        }
        bool f = fb[n] != 0;
        float v1 = f ? d1 * scale : NEG;
        float v2 = f ? d2 * scale : NEG;
        s1[n] = v1; s2[n] = v2;
        m1l = fmaxf(m1l, v1);
        m2l = fmaxf(m2l, v2);
    }
    __syncthreads();

    float m1 = blk_max(m1l, red, tid);
    float m2 = blk_max(m2l, red, tid);

    float z1l = 0.f, z2l = 0.f;
    for (int n = tid; n < NN; n += 256) {
        float p1 = expf(s1[n] - m1);
        float p2 = expf(s2[n] - m2);
        s1[n] = p1; s2[n] = p2;
        z1l += p1; z2l += p2;
    }
    __syncthreads();
    float Z1 = blk_sum(z1l, red, tid);
    float Z2 = blk_sum(z2l, red, tid);

    // V accumulation: warp w handles n = w, w+8, ...; lane = d (coalesced 128B rows)
    int w = tid >> 5, lane = tid & 31;
    const float* Vb = V + (size_t)(b * HH + h) * NN * DHH;
    float a1 = 0.f, a2 = 0.f;
#pragma unroll 10
    for (int n = w; n < NN; n += 8) {
        float v = Vb[n * DHH + lane];
        a1 = fmaf(s1[n], v, a1);
        a2 = fmaf(s2[n], v, a2);
    }
    __syncthreads();
    s1[tid] = a1;
    s2[tid] = a2;
    __syncthreads();
    if (tid < 64) {
        int qi = tid >> 5, l = tid & 31;
        const float* sr = qi ? s2 : s1;
        float sum = 0.f;
#pragma unroll
        for (int ww = 0; ww < 8; ww++) sum += sr[ww * 32 + l];
        if (qi == 0) g_att1[b * DD + h * DHH + l] = sum / Z1;
        else         g_att2[b * DD + h * DHH + l] = sum / Z2;
    }
}

// ---------------------------------------------------------------------------
// Phase 2.5 (tiled): glimpse = att1 @ W_out ; head_encoding = att2 @ W_sa
// grid = (16 batch-groups, 8 col-chunks), block = 256, dynamic smem 96KB.
// ---------------------------------------------------------------------------
__global__ void proj2_kernel(const float* __restrict__ Wout,
                             const float* __restrict__ Wsa,
                             float* __restrict__ out_head) {
    extern __shared__ float sm[];
    float* WoS = sm;              // 256*32
    float* WsS = sm + 8192;       // 256*32
    float* A1  = sm + 16384;      // 16*256
    float* A2  = sm + 20480;      // 16*256
    int bg = blockIdx.x, cc = blockIdx.y;
    int t = threadIdx.x;
    int j0 = cc * 32, b0 = bg * 16;

    for (int idx = t; idx < 8192; idx += 256) {
        int r = idx >> 5, c = idx & 31;
        WoS[idx] = Wout[r * DD + j0 + c];
        WsS[idx] = Wsa[r * DD + j0 + c];
    }
    for (int idx = t; idx < 4096; idx += 256) {
        int b = idx >> 8, i = idx & 255;
        A1[idx] = g_att1[(b0 + b) * DD + i];
        A2[idx] = g_att2[(b0 + b) * DD + i];
    }
    __syncthreads();

    int c = t & 31, bp = t >> 5;
    const float* a1A = A1 + bp * 256;
    const float* a2A = A2 + bp * 256;
    const float* a1B = A1 + (bp + 8) * 256;
    const float* a2B = A2 + (bp + 8) * 256;
    float g0 = 0.f, h0 = 0.f, g1 = 0.f, h1 = 0.f;
#pragma unroll 8
    for (int i = 0; i < 256; i++) {
        float wo = WoS[i * 32 + c];
        float ws = WsS[i * 32 + c];
        g0 = fmaf(a1A[i], wo, g0);
        h0 = fmaf(a2A[i], ws, h0);
        g1 = fmaf(a1B[i], wo, g1);
        h1 = fmaf(a2B[i], ws, h1);
    }
    int j = j0 + c;
    int bA = b0 + bp, bB = bA + 8;
    g_glimpse[bA * DD + j] = g0;
    g_glimpse[bB * DD + j] = g1;
    out_head[bA * DD + j] = h0;
    out_head[bB * DD + j] = h1;
}

// ---------------------------------------------------------------------------
// Phase 3: logits + tanh clip + mask + log_softmax.
// grid = B, block = 1024 (one row per thread, registers only).
// ---------------------------------------------------------------------------
__global__ void logits_kernel(const float* __restrict__ LK,
                              float* __restrict__ out_logp) {
    int b = blockIdx.x, tid = threadIdx.x;
    __shared__ float gl[DD];
    __shared__ float wred[32];
    __shared__ float bc1, bc2;

    if (tid < DD) gl[tid] = g_glimpse[b * DD + tid];
    __syncthreads();

    float l = NEG;
    if (tid < NN) {
        const float4* r = (const float4*)(LK + ((size_t)b * NN + tid) * DD);
        const float4* gv = (const float4*)gl;
        float d = 0.f;
#pragma unroll 8
        for (int i = 0; i < 64; i++) {
            float4 kv = r[i];
            float4 g = gv[i];
            d = fmaf(kv.x, g.x, d);
            d = fmaf(kv.y, g.y, d);
            d = fmaf(kv.z, g.z, d);
            d = fmaf(kv.w, g.w, d);
        }
        float lg = 10.0f * tanhf(d * 0.0625f);
        l = g_feas[b * NN + tid] ? lg : NEG;
    }

    // block max over 1024 threads
    float v = l;
#pragma unroll
    for (int o = 16; o; o >>= 1) v = fmaxf(v, __shfl_xor_sync(0xffffffffu, v, o));
    if ((tid & 31) == 0) wred[tid >> 5] = v;
    __syncthreads();
    if (tid < 32) {
        float x = wred[tid];
#pragma unroll
        for (int o = 16; o; o >>= 1) x = fmaxf(x, __shfl_xor_sync(0xffffffffu, x, o));
        if (tid == 0) bc1 = x;
    }
    __syncthreads();
    float m = bc1;

    float e = (tid < NN) ? expf(l - m) : 0.f;
    float s = e;
#pragma unroll
    for (int o = 16; o; o >>= 1) s += __shfl_xor_sync(0xffffffffu, s, o);
    __syncthreads();            // all reads of wred done before rewrite
    if ((tid & 31) == 0) wred[tid >> 5] = s;
    __syncthreads();
    if (tid < 32) {
        float x = wred[tid];
#pragma unroll
        for (int o = 16; o; o >>= 1) x += __shfl_xor_sync(0xffffffffu, x, o);
        if (tid == 0) bc2 = x;
    }
    __syncthreads();
    float lse = m + logf(bc2);

    if (tid < NN) out_logp[b * NN + tid] = l - lse;
}

// ---------------------------------------------------------------------------
extern "C" void kernel_launch(void* const* d_in, const int* in_sizes, int n_in,
                              void* d_out, int out_size) {
    const float* node_emb  = (const float*)d_in[0];
    const float* graph_ctx = (const float*)d_in[1];
    const float* K         = (const float*)d_in[2];
    const float* V         = (const float*)d_in[3];
    const float* LK        = (const float*)d_in[4];
    const float* cap       = (const float*)d_in[5];
    const float* rd        = (const float*)d_in[6];
    const float* rn        = (const float*)d_in[7];
    const float* Wc        = (const float*)d_in[8];
    const float* Wout      = (const float*)d_in[9];
    const float* Wsa       = (const float*)d_in[10];
    const int*   head      = (const int*)d_in[11];
    const int*   feasible  = (const int*)d_in[12];
    float* out = (float*)d_out;

    static bool attr_done = false;
    if (!attr_done) {
        cudaFuncSetAttribute(ctx2_kernel,  cudaFuncAttributeMaxDynamicSharedMemorySize, 98880);
        cudaFuncSetAttribute(proj2_kernel, cudaFuncAttributeMaxDynamicSharedMemorySize, 98304);
        attr_done = true;
    }

    feas_kernel<<<BB, 256>>>(feasible);
    ctx2_kernel<<<dim3(16, 16), 256, 98880>>>(node_emb, graph_ctx, cap, rd, rn, Wc, head);
    attn_kernel<<<dim3(HH, BB), 256>>>(K, V);
    proj2_kernel<<<dim3(16, 8), 256, 98304>>>(Wout, Wsa, out + BB * NN);
    logits_kernel<<<BB, 1024>>>(LK, out);
}

// round 6
// speedup vs baseline: 1.4093x; 1.1566x over previous
#include <cuda_runtime.h>
#include <math.h>

#define BB 256
#define NN 1000
#define DD 256
#define HH 8
#define DHH 32
#define NEG (-1000000000.0f)

// Intermediates (device globals: no allocation allowed)
__device__ float g_q1[BB * DD];  // glimpse_q
__device__ float g_q2[BB * DD];  // head_in

// ---------------------------------------------------------------------------
// Phase 1 (tiled): step_context = concat(cur, graph_ctx, dyn) @ W_ctx
// grid = (16 batch-groups, 16 col-chunks), block = 256, dynamic smem ~99KB.
// ---------------------------------------------------------------------------
__global__ void ctx2_kernel(const float* __restrict__ node_emb,
                            const float* __restrict__ graph_ctx,
                            const float* __restrict__ cap,
                            const float* __restrict__ rd,
                            const float* __restrict__ rn,
                            const float* __restrict__ Wc,
                            const int* __restrict__ head) {
    extern __shared__ float sm[];
    float* Ws = sm;              // 515*32
    float* xs = sm + 515 * 32;   // 16*515
    int bg = blockIdx.x, cc = blockIdx.y;
    int t = threadIdx.x;
    int j0 = cc * 32, b0 = bg * 16;

    for (int idx = t; idx < 515 * 32; idx += 256) {
        int r = idx >> 5, c = idx & 31;
        Ws[idx] = Wc[r * 512 + j0 + c];
    }
    for (int b = 0; b < 16; b++) {
        int bA = b0 + b;
        int hd = head[bA];
        const float* emb = node_emb + ((size_t)bA * NN + hd) * DD;
        const float* gc = graph_ctx + bA * DD;
        for (int i = t; i < 515; i += 256) {
            float v;
            if (i < 256) v = emb[i];
            else if (i < 512) v = gc[i - 256];
            else v = (i == 512) ? cap[bA] : (i == 513) ? rd[bA] : rn[bA];
            xs[b * 515 + i] = v;
        }
    }
    __syncthreads();

    int c = t & 31, bp = t >> 5;
    const float* xA = xs + bp * 515;
    const float* xB = xs + (bp + 8) * 515;
    float a0 = 0.f, a1 = 0.f;
#pragma unroll 5
    for (int i = 0; i < 515; i++) {
        float w = Ws[i * 32 + c];
        a0 = fmaf(xA[i], w, a0);
        a1 = fmaf(xB[i], w, a1);
    }
    int j = j0 + c;
    int bA = b0 + bp, bB = bA + 8;
    if (j < 256) {
        g_q1[bA * DD + j] = a0;
        g_q1[bB * DD + j] = a1;
    } else {
        g_q2[bA * DD + j - 256] = a0;
        g_q2[bB * DD + j - 256] = a1;
    }
}

// ---------------------------------------------------------------------------
// Mega kernel: per-batch fused feas + dual-query MHA (8 heads) + proj + logits
// grid = B, block = 1024, dynamic smem ~70.8 KB, 2 blocks/SM.
// Shared layout (floats):
//   s1[8000] s2[8000] q1s[256] q2s[256] att1s[256] att2s[256] gls[256]
//   red1[32] red2[32] redz1[32] redz2[32] bc[2] ired[32 ints] feas[1024 B]
// ---------------------------------------------------------------------------
__global__ __launch_bounds__(1024, 2)
void mega_kernel(const float* __restrict__ K,
                 const float* __restrict__ V,
                 const float* __restrict__ LK,
                 const float* __restrict__ Wout,
                 const float* __restrict__ Wsa,
                 const int* __restrict__ feasible,
                 float* __restrict__ out_logp,
                 float* __restrict__ out_head) {
    extern __shared__ float sm[];
    float* s1    = sm;            // 8000
    float* s2    = sm + 8000;     // 8000
    float* q1s   = sm + 16000;    // 256
    float* q2s   = sm + 16256;    // 256
    float* att1s = sm + 16512;    // 256
    float* att2s = sm + 16768;    // 256
    float* gls   = sm + 17024;    // 256
    float* red1  = sm + 17280;    // 32
    float* red2  = sm + 17312;    // 32
    float* redz1 = sm + 17344;    // 32
    float* redz2 = sm + 17376;    // 32
    float* bc    = sm + 17408;    // 2 (+2 pad)
    int*   ired  = (int*)(sm + 17412);              // 32 ints
    unsigned char* feas = (unsigned char*)(sm + 17444); // 1024 bytes
    // total = (17444 + 256) * 4 = 70800 bytes

    int b = blockIdx.x;
    int t = threadIdx.x;
    int warp = t >> 5, lane = t & 31;

    // ---- load queries ----
    if (t < DD) { q1s[t] = g_q1[b * DD + t]; q2s[t] = g_q2[b * DD + t]; }

    // ---- feasibility + no-feasible fix ----
    int f = 0;
    if (t < NN) { f = (feasible[b * NN + t] != 0); feas[t] = (unsigned char)f; }
    else feas[t] = 0;
    int any = __any_sync(0xffffffffu, f);
    if (lane == 0) ired[warp] = any;
    __syncthreads();
    if (t == 0) {
        int a = 0;
#pragma unroll
        for (int i = 0; i < 32; i++) a |= ired[i];
        if (!a) feas[0] = 1;
    }
    __syncthreads();

    // ---- scores: 128 threads per head, dual query ----
    int h = t >> 7, hh = t & 127;
    const float4* Kb = (const float4*)(K + (size_t)(b * HH + h) * NN * DHH);
    const float4* q1v = (const float4*)(q1s + h * DHH);
    const float4* q2v = (const float4*)(q2s + h * DHH);
    const float scale = 0.17677669529663687f; // 1/sqrt(32)
    float m1l = NEG, m2l = NEG;
    for (int n = hh; n < NN; n += 128) {
        const float4* kr = Kb + n * 8;
        float d1 = 0.f, d2 = 0.f;
#pragma unroll
        for (int i = 0; i < 8; i++) {
            float4 kv = kr[i];
            float4 qa = q1v[i];
            float4 qb = q2v[i];
            d1 = fmaf(kv.x, qa.x, d1); d1 = fmaf(kv.y, qa.y, d1);
            d1 = fmaf(kv.z, qa.z, d1); d1 = fmaf(kv.w, qa.w, d1);
            d2 = fmaf(kv.x, qb.x, d2); d2 = fmaf(kv.y, qb.y, d2);
            d2 = fmaf(kv.z, qb.z, d2); d2 = fmaf(kv.w, qb.w, d2);
        }
        bool fe = feas[n] != 0;
        float v1 = fe ? d1 * scale : NEG;
        float v2 = fe ? d2 * scale : NEG;
        s1[h * NN + n] = v1; s2[h * NN + n] = v2;
        m1l = fmaxf(m1l, v1); m2l = fmaxf(m2l, v2);
    }
#pragma unroll
    for (int o = 16; o; o >>= 1) {
        m1l = fmaxf(m1l, __shfl_xor_sync(0xffffffffu, m1l, o));
        m2l = fmaxf(m2l, __shfl_xor_sync(0xffffffffu, m2l, o));
    }
    if (lane == 0) { red1[warp] = m1l; red2[warp] = m2l; }
    __syncthreads();
    float m1 = fmaxf(fmaxf(red1[h * 4], red1[h * 4 + 1]), fmaxf(red1[h * 4 + 2], red1[h * 4 + 3]));
    float m2 = fmaxf(fmaxf(red2[h * 4], red2[h * 4 + 1]), fmaxf(red2[h * 4 + 2], red2[h * 4 + 3]));

    // ---- exp + per-head Z ----
    float z1l = 0.f, z2l = 0.f;
    for (int n = hh; n < NN; n += 128) {
        float p1 = expf(s1[h * NN + n] - m1);
        float p2 = expf(s2[h * NN + n] - m2);
        s1[h * NN + n] = p1; s2[h * NN + n] = p2;
        z1l += p1; z2l += p2;
    }
#pragma unroll
    for (int o = 16; o; o >>= 1) {
        z1l += __shfl_xor_sync(0xffffffffu, z1l, o);
        z2l += __shfl_xor_sync(0xffffffffu, z2l, o);
    }
    if (lane == 0) { redz1[warp] = z1l; redz2[warp] = z2l; }
    __syncthreads();

    // ---- V pass: 4 warps per head, lane = d, coalesced rows ----
    int w4 = warp & 3;
    const float* Vb = V + (size_t)(b * HH + h) * NN * DHH;
    float a1 = 0.f, a2 = 0.f;
#pragma unroll 5
    for (int n = w4; n < NN; n += 4) {
        float v = Vb[n * DHH + lane];
        a1 = fmaf(s1[h * NN + n], v, a1);
        a2 = fmaf(s2[h * NN + n], v, a2);
    }
    __syncthreads();          // all warps done reading exp(s) from s1/s2
    s1[t] = a1;               // reuse: V partials
    s2[t] = a2;
    __syncthreads();
    if (t < 512) {
        int q = t >> 8, idx = t & 255;
        int h2 = idx >> 5, d = idx & 31;
        const float* sr = q ? s2 : s1;
        float sum = sr[h2 * 128 + d] + sr[h2 * 128 + 32 + d]
                  + sr[h2 * 128 + 64 + d] + sr[h2 * 128 + 96 + d];
        const float* rz = q ? redz2 : redz1;
        float Z = rz[h2 * 4] + rz[h2 * 4 + 1] + rz[h2 * 4 + 2] + rz[h2 * 4 + 3];
        if (q == 0) att1s[idx] = sum / Z;
        else        att2s[idx] = sum / Z;
    }
    __syncthreads();

    // ---- proj: glimpse = att1 @ Wout; head_enc = att2 @ Wsa ----
    {
        int half = t >> 8;  // 0..3
        int j = t & 255;
        float acc = 0.f;
        if (half < 2) {
            int i0 = half * 128;
            const float* wp = Wout + (size_t)i0 * DD + j;
#pragma unroll 8
            for (int i = 0; i < 128; i++) acc = fmaf(att1s[i0 + i], wp[i * DD], acc);
        } else {
            int i0 = (half - 2) * 128;
            const float* wp = Wsa + (size_t)i0 * DD + j;
#pragma unroll 8
            for (int i = 0; i < 128; i++) acc = fmaf(att2s[i0 + i], wp[i * DD], acc);
        }
        __syncthreads();      // att reads done before s1 reuse below? (att in att1s/att2s; s1 reuse safe)
        s1[t] = acc;          // reuse: proj partials
        __syncthreads();
        if (t < 256) gls[t] = s1[t] + s1[256 + t];
        else if (t < 512) out_head[b * DD + (t - 256)] = s1[512 + (t - 256)] + s1[768 + (t - 256)];
    }
    __syncthreads();

    // ---- logits + tanh clip + mask + log-softmax ----
    float l = NEG;
    if (t < NN) {
        const float4* r = (const float4*)(LK + ((size_t)b * NN + t) * DD);
        const float4* gv = (const float4*)gls;
        float d = 0.f;
#pragma unroll 8
        for (int i = 0; i < 64; i++) {
            float4 kv = r[i];
            float4 g = gv[i];
            d = fmaf(kv.x, g.x, d); d = fmaf(kv.y, g.y, d);
            d = fmaf(kv.z, g.z, d); d = fmaf(kv.w, g.w, d);
        }
        float lg = 10.0f * tanhf(d * 0.0625f);
        l = feas[t] ? lg : NEG;
    }
    float v = l;
#pragma unroll
    for (int o = 16; o; o >>= 1) v = fmaxf(v, __shfl_xor_sync(0xffffffffu, v, o));
    if (lane == 0) red1[warp] = v;
    __syncthreads();
    if (t < 32) {
        float x = red1[t];
#pragma unroll
        for (int o = 16; o; o >>= 1) x = fmaxf(x, __shfl_xor_sync(0xffffffffu, x, o));
        if (t == 0) bc[0] = x;
    }
    __syncthreads();
    float m = bc[0];
    float e = (t < NN) ? expf(l - m) : 0.f;
#pragma unroll
    for (int o = 16; o; o >>= 1) e += __shfl_xor_sync(0xffffffffu, e, o);
    if (lane == 0) red2[warp] = e;
    __syncthreads();
    if (t < 32) {
        float x = red2[t];
#pragma unroll
        for (int o = 16; o; o >>= 1) x += __shfl_xor_sync(0xffffffffu, x, o);
        if (t == 0) bc[1] = x;
    }
    __syncthreads();
    float lse = m + logf(bc[1]);
    if (t < NN) out_logp[b * NN + t] = l - lse;
}

// ---------------------------------------------------------------------------
extern "C" void kernel_launch(void* const* d_in, const int* in_sizes, int n_in,
                              void* d_out, int out_size) {
    const float* node_emb  = (const float*)d_in[0];
    const float* graph_ctx = (const float*)d_in[1];
    const float* K         = (const float*)d_in[2];
    const float* V         = (const float*)d_in[3];
    const float* LK        = (const float*)d_in[4];
    const float* cap       = (const float*)d_in[5];
    const float* rd        = (const float*)d_in[6];
    const float* rn        = (const float*)d_in[7];
    const float* Wc        = (const float*)d_in[8];
    const float* Wout      = (const float*)d_in[9];
    const float* Wsa       = (const float*)d_in[10];
    const int*   head      = (const int*)d_in[11];
    const int*   feasible  = (const int*)d_in[12];
    float* out = (float*)d_out;

    static bool attr_done = false;
    if (!attr_done) {
        cudaFuncSetAttribute(ctx2_kernel, cudaFuncAttributeMaxDynamicSharedMemorySize, 98880);
        cudaFuncSetAttribute(mega_kernel, cudaFuncAttributeMaxDynamicSharedMemorySize, 70912);
        attr_done = true;
    }

    ctx2_kernel<<<dim3(16, 16), 256, 98880>>>(node_emb, graph_ctx, cap, rd, rn, Wc, head);
    mega_kernel<<<BB, 1024, 70800>>>(K, V, LK, Wout, Wsa, feasible, out, out + BB * NN);
}

// round 7
// speedup vs baseline: 1.9079x; 1.3539x over previous
#include <cuda_runtime.h>
#include <math.h>

#define BB 256
#define NN 1000
#define DD 256
#define HH 8
#define DHH 32
#define NEG (-1000000000.0f)

// Intermediates (device globals: no allocation allowed)
__device__ float g_q1[BB * DD];  // glimpse_q
__device__ float g_q2[BB * DD];  // head_in

// ---------------------------------------------------------------------------
// Phase 1 (tiled): step_context = concat(cur, graph_ctx, dyn) @ W_ctx
// grid = (16 batch-groups, 16 col-chunks), block = 512 (1 batch x 1 col each),
// dynamic smem ~99KB.
// ---------------------------------------------------------------------------
__global__ void ctx2_kernel(const float* __restrict__ node_emb,
                            const float* __restrict__ graph_ctx,
                            const float* __restrict__ cap,
                            const float* __restrict__ rd,
                            const float* __restrict__ rn,
                            const float* __restrict__ Wc,
                            const int* __restrict__ head) {
    extern __shared__ float sm[];
    float* Ws = sm;              // 515*32
    float* xs = sm + 515 * 32;   // 16*515
    int bg = blockIdx.x, cc = blockIdx.y;
    int t = threadIdx.x;
    int j0 = cc * 32, b0 = bg * 16;

    for (int idx = t; idx < 515 * 32; idx += 512) {
        int r = idx >> 5, c = idx & 31;
        Ws[idx] = Wc[r * 512 + j0 + c];
    }
    for (int idx = t; idx < 16 * 515; idx += 512) {
        int b = idx / 515, i = idx - b * 515;
        int bA = b0 + b;
        float v;
        if (i < 256) {
            int hd = head[bA];
            v = node_emb[((size_t)bA * NN + hd) * DD + i];
        } else if (i < 512) v = graph_ctx[bA * DD + (i - 256)];
        else v = (i == 512) ? cap[bA] : (i == 513) ? rd[bA] : rn[bA];
        xs[idx] = v;
    }
    __syncthreads();

    int c = t & 31, bp = t >> 5;   // bp in 0..15
    const float* xA = xs + bp * 515;
    float a0 = 0.f;
#pragma unroll 5
    for (int i = 0; i < 515; i++)
        a0 = fmaf(xA[i], Ws[i * 32 + c], a0);
    int j = j0 + c;
    int bA = b0 + bp;
    if (j < 256) g_q1[bA * DD + j] = a0;
    else         g_q2[bA * DD + j - 256] = a0;
}

// ---------------------------------------------------------------------------
// Mega kernel: per-batch fused feas + dual-query MHA (8 heads) + proj + logits
// grid = B, block = 1024, dynamic smem ~70.8 KB, 2 blocks/SM.
// ---------------------------------------------------------------------------
__global__ __launch_bounds__(1024, 2)
void mega_kernel(const float* __restrict__ K,
                 const float* __restrict__ V,
                 const float* __restrict__ LK,
                 const float* __restrict__ Wout,
                 const float* __restrict__ Wsa,
                 const int* __restrict__ feasible,
                 float* __restrict__ out_logp,
                 float* __restrict__ out_head) {
    extern __shared__ float sm[];
    float* s1    = sm;            // 8000
    float* s2    = sm + 8000;     // 8000
    float* q1s   = sm + 16000;    // 256
    float* q2s   = sm + 16256;    // 256
    float* att1s = sm + 16512;    // 256
    float* att2s = sm + 16768;    // 256
    float* gls   = sm + 17024;    // 256
    float* red1  = sm + 17280;    // 32
    float* red2  = sm + 17312;    // 32
    float* redz1 = sm + 17344;    // 32
    float* redz2 = sm + 17376;    // 32
    float* bc    = sm + 17408;    // 2 (+2 pad)
    int*   ired  = (int*)(sm + 17412);                  // 32 ints
    unsigned char* feas = (unsigned char*)(sm + 17444); // 1024 bytes
    // total = (17444 + 256) * 4 = 70800 bytes

    int b = blockIdx.x;
    int t = threadIdx.x;
    int warp = t >> 5, lane = t & 31;

    // ---- load queries ----
    if (t < DD) { q1s[t] = g_q1[b * DD + t]; q2s[t] = g_q2[b * DD + t]; }

    // ---- feasibility + no-feasible fix ----
    int f = 0;
    if (t < NN) { f = (feasible[b * NN + t] != 0); feas[t] = (unsigned char)f; }
    else feas[t] = 0;
    int any = __any_sync(0xffffffffu, f);
    if (lane == 0) ired[warp] = any;
    __syncthreads();
    if (t == 0) {
        int a = 0;
#pragma unroll
        for (int i = 0; i < 32; i++) a |= ired[i];
        if (!a) feas[0] = 1;
    }
    __syncthreads();

    // ---- scores: coalesced. Head h = warp>>2; warp covers 4 rows per LDG.128.
    // lane l: row = base + (l>>3), float4-chunk = l&7.
    int h = warp >> 2, w4 = warp & 3;
    int hh = t & 127;
    const float4* Kb = (const float4*)(K + (size_t)(b * HH + h) * NN * DHH);
    float4 qa = ((const float4*)(q1s + h * DHH))[lane & 7];
    float4 qb = ((const float4*)(q2s + h * DHH))[lane & 7];
    const float scale = 0.17677669529663687f; // 1/sqrt(32)
    float m1l = NEG, m2l = NEG;
    int rsub = lane >> 3;         // 0..3
    for (int i = 0; i < 63; i++) {
        int n = w4 * 4 + i * 16 + rsub;
        if (n < NN) {
            float4 kv = Kb[n * 8 + (lane & 7)];
            float d1 = fmaf(kv.x, qa.x, fmaf(kv.y, qa.y, fmaf(kv.z, qa.z, kv.w * qa.w)));
            float d2 = fmaf(kv.x, qb.x, fmaf(kv.y, qb.y, fmaf(kv.z, qb.z, kv.w * qb.w)));
            // reduce across the 8 lanes of this row
#pragma unroll
            for (int o = 4; o; o >>= 1) {
                d1 += __shfl_xor_sync(0xffffffffu, d1, o);
                d2 += __shfl_xor_sync(0xffffffffu, d2, o);
            }
            if ((lane & 7) == 0) {
                bool fe = feas[n] != 0;
                float v1 = fe ? d1 * scale : NEG;
                float v2 = fe ? d2 * scale : NEG;
                s1[h * NN + n] = v1; s2[h * NN + n] = v2;
                m1l = fmaxf(m1l, v1); m2l = fmaxf(m2l, v2);
            }
        } else {
            // keep shfl participation uniform
#pragma unroll
            for (int o = 4; o; o >>= 1) {
                (void)__shfl_xor_sync(0xffffffffu, 0.f, o);
                (void)__shfl_xor_sync(0xffffffffu, 0.f, o);
            }
        }
    }
#pragma unroll
    for (int o = 16; o; o >>= 1) {
        m1l = fmaxf(m1l, __shfl_xor_sync(0xffffffffu, m1l, o));
        m2l = fmaxf(m2l, __shfl_xor_sync(0xffffffffu, m2l, o));
    }
    if (lane == 0) { red1[warp] = m1l; red2[warp] = m2l; }
    __syncthreads();
    float m1 = fmaxf(fmaxf(red1[h * 4], red1[h * 4 + 1]), fmaxf(red1[h * 4 + 2], red1[h * 4 + 3]));
    float m2 = fmaxf(fmaxf(red2[h * 4], red2[h * 4 + 1]), fmaxf(red2[h * 4 + 2], red2[h * 4 + 3]));

    // ---- exp + per-head Z (128 threads per head, stride over NN) ----
    float z1l = 0.f, z2l = 0.f;
    for (int n = hh; n < NN; n += 128) {
        float p1 = expf(s1[h * NN + n] - m1);
        float p2 = expf(s2[h * NN + n] - m2);
        s1[h * NN + n] = p1; s2[h * NN + n] = p2;
        z1l += p1; z2l += p2;
    }
#pragma unroll
    for (int o = 16; o; o >>= 1) {
        z1l += __shfl_xor_sync(0xffffffffu, z1l, o);
        z2l += __shfl_xor_sync(0xffffffffu, z2l, o);
    }
    if (lane == 0) { redz1[warp] = z1l; redz2[warp] = z2l; }
    __syncthreads();

    // ---- V pass: 4 warps per head, lane = d (coalesced 128B rows) ----
    const float* Vb = V + (size_t)(b * HH + h) * NN * DHH;
    float a1 = 0.f, a2 = 0.f;
#pragma unroll 5
    for (int n = w4; n < NN; n += 4) {
        float v = Vb[n * DHH + lane];
        a1 = fmaf(s1[h * NN + n], v, a1);
        a2 = fmaf(s2[h * NN + n], v, a2);
    }
    __syncthreads();          // all warps done reading exp(s) from s1/s2
    s1[t] = a1;               // reuse: V partials
    s2[t] = a2;
    __syncthreads();
    if (t < 512) {
        int q = t >> 8, idx = t & 255;
        int h2 = idx >> 5, d = idx & 31;
        const float* sr = q ? s2 : s1;
        float sum = sr[h2 * 128 + d] + sr[h2 * 128 + 32 + d]
                  + sr[h2 * 128 + 64 + d] + sr[h2 * 128 + 96 + d];
        const float* rz = q ? redz2 : redz1;
        float Z = rz[h2 * 4] + rz[h2 * 4 + 1] + rz[h2 * 4 + 2] + rz[h2 * 4 + 3];
        if (q == 0) att1s[idx] = sum / Z;
        else        att2s[idx] = sum / Z;
    }
    __syncthreads();

    // ---- proj: glimpse = att1 @ Wout; head_enc = att2 @ Wsa ----
    {
        int half = t >> 8;  // 0..3
        int j = t & 255;
        float acc = 0.f;
        if (half < 2) {
            int i0 = half * 128;
            const float* wp = Wout + (size_t)i0 * DD + j;
#pragma unroll 8
            for (int i = 0; i < 128; i++) acc = fmaf(att1s[i0 + i], wp[i * DD], acc);
        } else {
            int i0 = (half - 2) * 128;
            const float* wp = Wsa + (size_t)i0 * DD + j;
#pragma unroll 8
            for (int i = 0; i < 128; i++) acc = fmaf(att2s[i0 + i], wp[i * DD], acc);
        }
        __syncthreads();
        s1[t] = acc;          // reuse: proj partials
        __syncthreads();
        if (t < 256) gls[t] = s1[t] + s1[256 + t];
        else if (t < 512) out_head[b * DD + (t - 256)] = s1[512 + (t - 256)] + s1[768 + (t - 256)];
    }
    __syncthreads();

    // ---- logits: coalesced. Warp covers 2 rows/iter; lane l: row = l>>4,
    // 16 lanes sweep the 1KB row in 4 LDG.128. ----
    int rhalf = lane >> 4;        // 0 or 1
    int csel = lane & 15;         // float4 chunk within group
    const float4* gv = (const float4*)gls;
    for (int k = 0; k < 16; k++) {
        int n = warp * 2 + k * 64 + rhalf;
        float d = 0.f;
        if (n < NN) {
            const float4* r = (const float4*)(LK + ((size_t)b * NN + n) * DD);
#pragma unroll
            for (int jj = 0; jj < 4; jj++) {
                float4 kv = r[csel + jj * 16];
                float4 g = gv[csel + jj * 16];
                d = fmaf(kv.x, g.x, d); d = fmaf(kv.y, g.y, d);
                d = fmaf(kv.z, g.z, d); d = fmaf(kv.w, g.w, d);
            }
        }
#pragma unroll
        for (int o = 8; o; o >>= 1) d += __shfl_xor_sync(0xffffffffu, d, o);
        if (csel == 0 && n < NN) {
            float lg = 10.0f * tanhf(d * 0.0625f);
            s1[n] = feas[n] ? lg : NEG;   // reuse s1: logits buffer
        }
    }
    __syncthreads();

    // ---- log-softmax over s1[0..999] ----
    float l = (t < NN) ? s1[t] : NEG;
    float v = l;
#pragma unroll
    for (int o = 16; o; o >>= 1) v = fmaxf(v, __shfl_xor_sync(0xffffffffu, v, o));
    if (lane == 0) red1[warp] = v;
    __syncthreads();
    if (t < 32) {
        float x = red1[t];
#pragma unroll
        for (int o = 16; o; o >>= 1) x = fmaxf(x, __shfl_xor_sync(0xffffffffu, x, o));
        if (t == 0) bc[0] = x;
    }
    __syncthreads();
    float m = bc[0];
    float e = (t < NN) ? expf(l - m) : 0.f;
#pragma unroll
    for (int o = 16; o; o >>= 1) e += __shfl_xor_sync(0xffffffffu, e, o);
    if (lane == 0) red2[warp] = e;
    __syncthreads();
    if (t < 32) {
        float x = red2[t];
#pragma unroll
        for (int o = 16; o; o >>= 1) x += __shfl_xor_sync(0xffffffffu, x, o);
        if (t == 0) bc[1] = x;
    }
    __syncthreads();
    float lse = m + logf(bc[1]);
    if (t < NN) out_logp[b * NN + t] = l - lse;
}

// ---------------------------------------------------------------------------
extern "C" void kernel_launch(void* const* d_in, const int* in_sizes, int n_in,
                              void* d_out, int out_size) {
    const float* node_emb  = (const float*)d_in[0];
    const float* graph_ctx = (const float*)d_in[1];
    const float* K         = (const float*)d_in[2];
    const float* V         = (const float*)d_in[3];
    const float* LK        = (const float*)d_in[4];
    const float* cap       = (const float*)d_in[5];
    const float* rd        = (const float*)d_in[6];
    const float* rn        = (const float*)d_in[7];
    const float* Wc        = (const float*)d_in[8];
    const float* Wout      = (const float*)d_in[9];
    const float* Wsa       = (const float*)d_in[10];
    const int*   head      = (const int*)d_in[11];
    const int*   feasible  = (const int*)d_in[12];
    float* out = (float*)d_out;

    static bool attr_done = false;
    if (!attr_done) {
        cudaFuncSetAttribute(ctx2_kernel, cudaFuncAttributeMaxDynamicSharedMemorySize, 98880);
        cudaFuncSetAttribute(mega_kernel, cudaFuncAttributeMaxDynamicSharedMemorySize, 70912);
        attr_done = true;
    }

    ctx2_kernel<<<dim3(16, 16), 512, 98880>>>(node_emb, graph_ctx, cap, rd, rn, Wc, head);
    mega_kernel<<<BB, 1024, 70800>>>(K, V, LK, Wout, Wsa, feasible, out, out + BB * NN);
}

// round 8
// speedup vs baseline: 1.9110x; 1.0016x over previous
#include <cuda_runtime.h>
#include <math.h>

#define BB 256
#define NN 1000
#define DD 256
#define HH 8
#define DHH 32
#define NEG (-1000000000.0f)

// Intermediates (device globals: no allocation allowed)
__device__ float g_q1[BB * DD];  // glimpse_q
__device__ float g_q2[BB * DD];  // head_in

// ---------------------------------------------------------------------------
// Phase 1 (tiled): step_context = concat(cur, graph_ctx, dyn) @ W_ctx
// grid = (16 batch-groups, 16 col-chunks), block = 512 (1 batch x 1 col each),
// dynamic smem ~99KB.
// ---------------------------------------------------------------------------
__global__ void ctx2_kernel(const float* __restrict__ node_emb,
                            const float* __restrict__ graph_ctx,
                            const float* __restrict__ cap,
                            const float* __restrict__ rd,
                            const float* __restrict__ rn,
                            const float* __restrict__ Wc,
                            const int* __restrict__ head) {
    extern __shared__ float sm[];
    float* Ws = sm;              // 515*32
    float* xs = sm + 515 * 32;   // 16*515
    int bg = blockIdx.x, cc = blockIdx.y;
    int t = threadIdx.x;
    int j0 = cc * 32, b0 = bg * 16;

    for (int idx = t; idx < 515 * 32; idx += 512) {
        int r = idx >> 5, c = idx & 31;
        Ws[idx] = Wc[r * 512 + j0 + c];
    }
    for (int idx = t; idx < 16 * 515; idx += 512) {
        int b = idx / 515, i = idx - b * 515;
        int bA = b0 + b;
        float v;
        if (i < 256) {
            int hd = head[bA];
            v = node_emb[((size_t)bA * NN + hd) * DD + i];
        } else if (i < 512) v = graph_ctx[bA * DD + (i - 256)];
        else v = (i == 512) ? cap[bA] : (i == 513) ? rd[bA] : rn[bA];
        xs[idx] = v;
    }
    __syncthreads();

    int c = t & 31, bp = t >> 5;   // bp in 0..15
    const float* xA = xs + bp * 515;
    float a0 = 0.f;
#pragma unroll 5
    for (int i = 0; i < 515; i++)
        a0 = fmaf(xA[i], Ws[i * 32 + c], a0);
    int j = j0 + c;
    int bA = b0 + bp;
    if (j < 256) g_q1[bA * DD + j] = a0;
    else         g_q2[bA * DD + j - 256] = a0;
}

// ---------------------------------------------------------------------------
// Mega kernel: per-batch fused feas + dual-query MHA (8 heads) + proj + logits
// grid = B, block = 1024, dynamic smem ~70.8 KB, 2 blocks/SM.
// ---------------------------------------------------------------------------
__global__ __launch_bounds__(1024, 2)
void mega_kernel(const float* __restrict__ K,
                 const float* __restrict__ V,
                 const float* __restrict__ LK,
                 const float* __restrict__ Wout,
                 const float* __restrict__ Wsa,
                 const int* __restrict__ feasible,
                 float* __restrict__ out_logp,
                 float* __restrict__ out_head) {
    extern __shared__ float sm[];
    float* s1    = sm;            // 8000
    float* s2    = sm + 8000;     // 8000
    float* q1s   = sm + 16000;    // 256
    float* q2s   = sm + 16256;    // 256
    float* att1s = sm + 16512;    // 256
    float* att2s = sm + 16768;    // 256
    float* gls   = sm + 17024;    // 256
    float* red1  = sm + 17280;    // 32
    float* red2  = sm + 17312;    // 32
    float* redz1 = sm + 17344;    // 32
    float* redz2 = sm + 17376;    // 32
    float* bc    = sm + 17408;    // 2 (+2 pad)
    int*   ired  = (int*)(sm + 17412);                  // 32 ints
    unsigned char* feas = (unsigned char*)(sm + 17444); // 1024 bytes
    // total = (17444 + 256) * 4 = 70800 bytes

    int b = blockIdx.x;
    int t = threadIdx.x;
    int warp = t >> 5, lane = t & 31;

    // ---- load queries ----
    if (t < DD) { q1s[t] = g_q1[b * DD + t]; q2s[t] = g_q2[b * DD + t]; }

    // ---- feasibility + no-feasible fix ----
    int f = 0;
    if (t < NN) { f = (feasible[b * NN + t] != 0); feas[t] = (unsigned char)f; }
    else feas[t] = 0;
    int any = __any_sync(0xffffffffu, f);
    if (lane == 0) ired[warp] = any;
    __syncthreads();
    if (t == 0) {
        int a = 0;
#pragma unroll
        for (int i = 0; i < 32; i++) a |= ired[i];
        if (!a) feas[0] = 1;
    }
    __syncthreads();

    // ---- scores: coalesced. Head h = warp>>2; warp covers 4 rows per LDG.128.
    // lane l: row = base + (l>>3), float4-chunk = l&7.
    int h = warp >> 2, w4 = warp & 3;
    int hh = t & 127;
    const float4* Kb = (const float4*)(K + (size_t)(b * HH + h) * NN * DHH);
    float4 qa = ((const float4*)(q1s + h * DHH))[lane & 7];
    float4 qb = ((const float4*)(q2s + h * DHH))[lane & 7];
    const float scale = 0.17677669529663687f; // 1/sqrt(32)
    float m1l = NEG, m2l = NEG;
    int rsub = lane >> 3;         // 0..3
    for (int i = 0; i < 63; i++) {
        int n = w4 * 4 + i * 16 + rsub;
        if (n < NN) {
            float4 kv = Kb[n * 8 + (lane & 7)];
            float d1 = fmaf(kv.x, qa.x, fmaf(kv.y, qa.y, fmaf(kv.z, qa.z, kv.w * qa.w)));
            float d2 = fmaf(kv.x, qb.x, fmaf(kv.y, qb.y, fmaf(kv.z, qb.z, kv.w * qb.w)));
            // reduce across the 8 lanes of this row
#pragma unroll
            for (int o = 4; o; o >>= 1) {
                d1 += __shfl_xor_sync(0xffffffffu, d1, o);
                d2 += __shfl_xor_sync(0xffffffffu, d2, o);
            }
            if ((lane & 7) == 0) {
                bool fe = feas[n] != 0;
                float v1 = fe ? d1 * scale : NEG;
                float v2 = fe ? d2 * scale : NEG;
                s1[h * NN + n] = v1; s2[h * NN + n] = v2;
                m1l = fmaxf(m1l, v1); m2l = fmaxf(m2l, v2);
            }
        } else {
            // keep shfl participation uniform
#pragma unroll
            for (int o = 4; o; o >>= 1) {
                (void)__shfl_xor_sync(0xffffffffu, 0.f, o);
                (void)__shfl_xor_sync(0xffffffffu, 0.f, o);
            }
        }
    }
#pragma unroll
    for (int o = 16; o; o >>= 1) {
        m1l = fmaxf(m1l, __shfl_xor_sync(0xffffffffu, m1l, o));
        m2l = fmaxf(m2l, __shfl_xor_sync(0xffffffffu, m2l, o));
    }
    if (lane == 0) { red1[warp] = m1l; red2[warp] = m2l; }
    __syncthreads();
    float m1 = fmaxf(fmaxf(red1[h * 4], red1[h * 4 + 1]), fmaxf(red1[h * 4 + 2], red1[h * 4 + 3]));
    float m2 = fmaxf(fmaxf(red2[h * 4], red2[h * 4 + 1]), fmaxf(red2[h * 4 + 2], red2[h * 4 + 3]));

    // ---- exp + per-head Z (128 threads per head, stride over NN) ----
    float z1l = 0.f, z2l = 0.f;
    for (int n = hh; n < NN; n += 128) {
        float p1 = expf(s1[h * NN + n] - m1);
        float p2 = expf(s2[h * NN + n] - m2);
        s1[h * NN + n] = p1; s2[h * NN + n] = p2;
        z1l += p1; z2l += p2;
    }
#pragma unroll
    for (int o = 16; o; o >>= 1) {
        z1l += __shfl_xor_sync(0xffffffffu, z1l, o);
        z2l += __shfl_xor_sync(0xffffffffu, z2l, o);
    }
    if (lane == 0) { redz1[warp] = z1l; redz2[warp] = z2l; }
    __syncthreads();

    // ---- V pass: 4 warps per head, lane = d (coalesced 128B rows) ----
    const float* Vb = V + (size_t)(b * HH + h) * NN * DHH;
    float a1 = 0.f, a2 = 0.f;
#pragma unroll 5
    for (int n = w4; n < NN; n += 4) {
        float v = Vb[n * DHH + lane];
        a1 = fmaf(s1[h * NN + n], v, a1);
        a2 = fmaf(s2[h * NN + n], v, a2);
    }
    __syncthreads();          // all warps done reading exp(s) from s1/s2
    s1[t] = a1;               // reuse: V partials
    s2[t] = a2;
    __syncthreads();
    if (t < 512) {
        int q = t >> 8, idx = t & 255;
        int h2 = idx >> 5, d = idx & 31;
        const float* sr = q ? s2 : s1;
        float sum = sr[h2 * 128 + d] + sr[h2 * 128 + 32 + d]
                  + sr[h2 * 128 + 64 + d] + sr[h2 * 128 + 96 + d];
        const float* rz = q ? redz2 : redz1;
        float Z = rz[h2 * 4] + rz[h2 * 4 + 1] + rz[h2 * 4 + 2] + rz[h2 * 4 + 3];
        if (q == 0) att1s[idx] = sum / Z;
        else        att2s[idx] = sum / Z;
    }
    __syncthreads();

    // ---- proj: glimpse = att1 @ Wout; head_enc = att2 @ Wsa ----
    {
        int half = t >> 8;  // 0..3
        int j = t & 255;
        float acc = 0.f;
        if (half < 2) {
            int i0 = half * 128;
            const float* wp = Wout + (size_t)i0 * DD + j;
#pragma unroll 8
            for (int i = 0; i < 128; i++) acc = fmaf(att1s[i0 + i], wp[i * DD], acc);
        } else {
            int i0 = (half - 2) * 128;
            const float* wp = Wsa + (size_t)i0 * DD + j;
#pragma unroll 8
            for (int i = 0; i < 128; i++) acc = fmaf(att2s[i0 + i], wp[i * DD], acc);
        }
        __syncthreads();
        s1[t] = acc;          // reuse: proj partials
        __syncthreads();
        if (t < 256) gls[t] = s1[t] + s1[256 + t];
        else if (t < 512) out_head[b * DD + (t - 256)] = s1[512 + (t - 256)] + s1[768 + (t - 256)];
    }
    __syncthreads();

    // ---- logits: coalesced. Warp covers 2 rows/iter; lane l: row = l>>4,
    // 16 lanes sweep the 1KB row in 4 LDG.128. ----
    int rhalf = lane >> 4;        // 0 or 1
    int csel = lane & 15;         // float4 chunk within group
    const float4* gv = (const float4*)gls;
    for (int k = 0; k < 16; k++) {
        int n = warp * 2 + k * 64 + rhalf;
        float d = 0.f;
        if (n < NN) {
            const float4* r = (const float4*)(LK + ((size_t)b * NN + n) * DD);
#pragma unroll
            for (int jj = 0; jj < 4; jj++) {
                float4 kv = r[csel + jj * 16];
                float4 g = gv[csel + jj * 16];
                d = fmaf(kv.x, g.x, d); d = fmaf(kv.y, g.y, d);
                d = fmaf(kv.z, g.z, d); d = fmaf(kv.w, g.w, d);
            }
        }
#pragma unroll
        for (int o = 8; o; o >>= 1) d += __shfl_xor_sync(0xffffffffu, d, o);
        if (csel == 0 && n < NN) {
            float lg = 10.0f * tanhf(d * 0.0625f);
            s1[n] = feas[n] ? lg : NEG;   // reuse s1: logits buffer
        }
    }
    __syncthreads();

    // ---- log-softmax over s1[0..999] ----
    float l = (t < NN) ? s1[t] : NEG;
    float v = l;
#pragma unroll
    for (int o = 16; o; o >>= 1) v = fmaxf(v, __shfl_xor_sync(0xffffffffu, v, o));
    if (lane == 0) red1[warp] = v;
    __syncthreads();
    if (t < 32) {
        float x = red1[t];
#pragma unroll
        for (int o = 16; o; o >>= 1) x = fmaxf(x, __shfl_xor_sync(0xffffffffu, x, o));
        if (t == 0) bc[0] = x;
    }
    __syncthreads();
    float m = bc[0];
    float e = (t < NN) ? expf(l - m) : 0.f;
#pragma unroll
    for (int o = 16; o; o >>= 1) e += __shfl_xor_sync(0xffffffffu, e, o);
    if (lane == 0) red2[warp] = e;
    __syncthreads();
    if (t < 32) {
        float x = red2[t];
#pragma unroll
        for (int o = 16; o; o >>= 1) x += __shfl_xor_sync(0xffffffffu, x, o);
        if (t == 0) bc[1] = x;
    }
    __syncthreads();
    float lse = m + logf(bc[1]);
    if (t < NN) out_logp[b * NN + t] = l - lse;
}

// ---------------------------------------------------------------------------
extern "C" void kernel_launch(void* const* d_in, const int* in_sizes, int n_in,
                              void* d_out, int out_size) {
    const float* node_emb  = (const float*)d_in[0];
    const float* graph_ctx = (const float*)d_in[1];
    const float* K         = (const float*)d_in[2];
    const float* V         = (const float*)d_in[3];
    const float* LK        = (const float*)d_in[4];
    const float* cap       = (const float*)d_in[5];
    const float* rd        = (const float*)d_in[6];
    const float* rn        = (const float*)d_in[7];
    const float* Wc        = (const float*)d_in[8];
    const float* Wout      = (const float*)d_in[9];
    const float* Wsa       = (const float*)d_in[10];
    const int*   head      = (const int*)d_in[11];
    const int*   feasible  = (const int*)d_in[12];
    float* out = (float*)d_out;

    static bool attr_done = false;
    if (!attr_done) {
        cudaFuncSetAttribute(ctx2_kernel, cudaFuncAttributeMaxDynamicSharedMemorySize, 98880);
        cudaFuncSetAttribute(mega_kernel, cudaFuncAttributeMaxDynamicSharedMemorySize, 70912);
        attr_done = true;
    }

    ctx2_kernel<<<dim3(16, 16), 512, 98880>>>(node_emb, graph_ctx, cap, rd, rn, Wc, head);
    mega_kernel<<<BB, 1024, 70800>>>(K, V, LK, Wout, Wsa, feasible, out, out + BB * NN);
}